// round 15
// baseline (speedup 1.0000x reference)
#include <cuda_runtime.h>
#include <cuda_fp16.h>
#include <cstdint>

#define BATCH 64
#define NCAP  16
#define DCAP  64
#define NIN   512
#define DIN   1024

// ---------------- scratch (allocation-free: __device__ globals) ----------------
__device__ __half g_xh[(size_t)BATCH * NIN * DIN];       // 64 MB, x f16 [b][j][k]
__device__ __half g_wh16[(size_t)DIN * NCAP * DCAP];     // 2 MB, W f16 [k][n]
__device__ float  g_xsump[8][BATCH][DIN];                // 2 MB, partial x sums over j
__device__ __half g_t16[(size_t)BATCH * NCAP * DIN];     // 2 MB, t f16 [b][i][k]
__device__ float  g_ypart[8][BATCH][NCAP][DIN];          // 32 MB, y partials

// ---------------- helpers ----------------
__device__ __forceinline__ uint32_t smem_u32(const void* p) {
    uint32_t a;
    asm("{ .reg .u64 t; cvta.to.shared.u64 t, %1; cvt.u32.u64 %0, t; }" : "=r"(a) : "l"(p));
    return a;
}
__device__ __forceinline__ void cp16(uint32_t dst, const void* src) {
    asm volatile("cp.async.cg.shared.global [%0], [%1], 16;\n" :: "r"(dst), "l"(src));
}
__device__ __forceinline__ void cp_commit() { asm volatile("cp.async.commit_group;\n" ::: "memory"); }

__device__ __forceinline__ void hmma(float* d, const uint32_t* a, const uint32_t* b) {
    asm volatile(
        "mma.sync.aligned.m16n8k16.row.col.f32.f16.f16.f32 "
        "{%0,%1,%2,%3}, {%4,%5,%6,%7}, {%8,%9}, {%0,%1,%2,%3};\n"
        : "+f"(d[0]), "+f"(d[1]), "+f"(d[2]), "+f"(d[3])
        : "r"(a[0]), "r"(a[1]), "r"(a[2]), "r"(a[3]), "r"(b[0]), "r"(b[1]));
}
__device__ __forceinline__ void ldsm_x4(uint32_t* r, uint32_t addr) {
    asm volatile("ldmatrix.sync.aligned.m8n8.x4.shared.b16 {%0,%1,%2,%3}, [%4];"
                 : "=r"(r[0]), "=r"(r[1]), "=r"(r[2]), "=r"(r[3]) : "r"(addr));
}
__device__ __forceinline__ void ldsm_x2(uint32_t* r, uint32_t addr) {
    asm volatile("ldmatrix.sync.aligned.m8n8.x2.shared.b16 {%0,%1}, [%2];"
                 : "=r"(r[0]), "=r"(r[1]) : "r"(addr));
}
__device__ __forceinline__ void ldsm_x2t(uint32_t* r, uint32_t addr) {
    asm volatile("ldmatrix.sync.aligned.m8n8.x2.trans.shared.b16 {%0,%1}, [%2];"
                 : "=r"(r[0]), "=r"(r[1]) : "r"(addr));
}

// ---------------- prep: W f32 -> f16 ----------------
__global__ __launch_bounds__(256) void wh16_kernel(const float* __restrict__ W) {
    const size_t n4 = (size_t)DIN * 1024 / 4;
    for (size_t e = (size_t)blockIdx.x * blockDim.x + threadIdx.x; e < n4;
         e += (size_t)gridDim.x * blockDim.x) {
        float4 v = ((const float4*)W)[e];
        __half2* dst = (__half2*)g_wh16 + e * 2;
        dst[0] = __floats2half2_rn(v.x, v.y);
        dst[1] = __floats2half2_rn(v.z, v.w);
    }
}

// ---------------- pass0: xsum partials + x -> f16 ----------------
__global__ __launch_bounds__(256) void pass0(const float* __restrict__ X) {
    const int c = blockIdx.x, b = blockIdx.y, tid = threadIdx.x;
    const size_t rowbase = ((size_t)b * NIN + c * 64) * DIN;
    const float4* xp = (const float4*)(X + rowbase) + tid;
    uint2* xh = (uint2*)(g_xh + rowbase) + tid;
    float4 a = make_float4(0.f, 0.f, 0.f, 0.f);
#pragma unroll 4
    for (int j = 0; j < 64; j++) {
        const float4 v = xp[j * (DIN / 4)];
        a.x += v.x; a.y += v.y; a.z += v.z; a.w += v.w;
        const __half2 h0 = __floats2half2_rn(v.x, v.y);
        const __half2 h1 = __floats2half2_rn(v.z, v.w);
        uint2 u;
        u.x = *(const unsigned*)&h0;
        u.y = *(const unsigned*)&h1;
        xh[j * (DIN / 4)] = u;
    }
    ((float4*)g_xsump[c][b])[tid] = a;
}

// ---------------- kA3: y -> z = y@W_i (mma) -> squash -> t16 = out@W_i^T (mma) ----------------
#define KAB 8
#define WPITB 144
#define YPITH 1032
#define ZPIT  68
#define OPITH 72
#define KY_OFF (DIN * WPITB)               // 147456
#define KZ_OFF (KY_OFF + 16 * YPITH * 2)   // 180480
#define KO_OFF (KZ_OFF + 2 * 8 * ZPIT * 4) // 184832
#define KA3_SMEM (KO_OFF + 16 * OPITH * 2) // 187136

__global__ __launch_bounds__(512) void kA3(float* __restrict__ d_out, int stage) {
    extern __shared__ char smb[];
    const uint32_t sb = smem_u32(smb);
    __half* y16   = (__half*)(smb + KY_OFF);
    float*  zp    = (float*)(smb + KZ_OFF);
    __half* out16 = (__half*)(smb + KO_OFF);

    const int i = blockIdx.x, bg = blockIdx.y, tid = threadIdx.x;
    const int b0 = bg * KAB;
    const int lane = tid & 31, w = tid >> 5;

    {
        const __half* src = g_wh16 + i * 64;
#pragma unroll 4
        for (int e = tid; e < 8192; e += 512) {
            const int k = e >> 3, c = e & 7;
            cp16(sb + k * WPITB + c * 16, src + (size_t)k * 1024 + c * 8);
        }
        cp_commit();
    }

    for (int e = tid; e < 16 * DIN; e += 512) {
        const int r = e >> 10, k = e & 1023;
        float v = 0.f;
        if (r < 8) {
            if (stage == 0) {
#pragma unroll
                for (int p = 0; p < 8; p++) v += g_xsump[p][b0 + r][k];
                v *= (1.f / 16.f);
            } else {
#pragma unroll
                for (int p = 0; p < 8; p++) v += g_ypart[p][b0 + r][i][k];
            }
        }
        y16[r * YPITH + k] = __float2half_rn(v);
    }
    asm volatile("cp.async.wait_group 0;\n" ::: "memory");
    __syncthreads();

    {
        const int kh = w & 1, nt = w >> 1;
        float acc[4] = {0.f, 0.f, 0.f, 0.f};
        const uint32_t a_base = sb + KY_OFF + (uint32_t)(lane & 15) * (YPITH * 2)
                               + ((lane >> 4) & 1) * 16 + kh * 1024;
        const uint32_t b_row0 = (uint32_t)(kh * 512 + (lane & 15));
#pragma unroll
        for (int s = 0; s < 32; s++) {
            uint32_t af[4], bf[2];
            ldsm_x4(af, a_base + s * 32);
            ldsm_x2t(bf, sb + (b_row0 + s * 16) * WPITB + nt * 16);
            hmma(acc, af, bf);
        }
        const int bl = lane >> 2, dc = nt * 8 + (lane & 3) * 2;
        zp[(kh * 8 + bl) * ZPIT + dc]     = acc[0];
        zp[(kh * 8 + bl) * ZPIT + dc + 1] = acc[1];
    }
    __syncthreads();

    if (tid < 256) {
        const int bl = w;
        const float za = zp[(0 * 8 + bl) * ZPIT + 2 * lane]     + zp[(1 * 8 + bl) * ZPIT + 2 * lane];
        const float zb = zp[(0 * 8 + bl) * ZPIT + 2 * lane + 1] + zp[(1 * 8 + bl) * ZPIT + 2 * lane + 1];
        float sq = za * za + zb * zb;
#pragma unroll
        for (int o = 16; o; o >>= 1) sq += __shfl_xor_sync(0xffffffffu, sq, o);
        const float inv = 1.0f / sqrtf(sq + 1e-7f);
        const float ox = za * inv, oy = zb * inv;
        *(half2*)&out16[bl * OPITH + 2 * lane] = __floats2half2_rn(ox, oy);
        if (stage == 2) {
            float2* dp = (float2*)(d_out + ((size_t)(b0 + bl) * NCAP + i) * DCAP);
            dp[lane] = make_float2(ox, oy);
        }
    } else {
        const int idx = tid - 256;
        const int r = 8 + (idx >> 5);
        *(half2*)&out16[r * OPITH + 2 * (idx & 31)] = __floats2half2_rn(0.f, 0.f);
    }
    __syncthreads();
    if (stage == 2) return;

    {
        uint32_t af[4][4];
        const uint32_t oa = sb + KO_OFF + (uint32_t)(lane & 15) * (OPITH * 2)
                           + ((lane >> 4) & 1) * 16;
#pragma unroll
        for (int s = 0; s < 4; s++) ldsm_x4(af[s], oa + s * 32);

        float ta[8][4];
#pragma unroll
        for (int nt = 0; nt < 8; nt++)
#pragma unroll
            for (int q = 0; q < 4; q++) ta[nt][q] = 0.f;

#pragma unroll
        for (int s = 0; s < 4; s++) {
#pragma unroll
            for (int nt = 0; nt < 8; nt++) {
                uint32_t bf[2];
                ldsm_x2(bf, sb + (uint32_t)(w * 64 + nt * 8 + (lane & 7)) * WPITB
                            + ((lane >> 3) & 1) * 16 + s * 32);
                hmma(ta[nt], af[s], bf);
            }
        }

        const int bl = lane >> 2;
#pragma unroll
        for (int nt = 0; nt < 8; nt++) {
            const int k = w * 64 + nt * 8 + (lane & 3) * 2;
            *(half2*)&g_t16[((size_t)(b0 + bl) * NCAP + i) * DIN + k] =
                __floats2half2_rn(ta[nt][0], ta[nt][1]);
        }
    }
}

// ---------------- pass_route5: JT=64, 3 CTAs/SM ----------------
#define JT5   64
#define XPB5  144
#define XBUF5 (JT5 * XPB5)                 // 9216
#define NBUF5 3
#define T_OFF5 (NBUF5 * XBUF5)             // 27648
#define TPB5  2064
#define CF_OFF5 (T_OFF5 + 16 * TPB5)       // 60672
#define CFP5  20
#define C16_OFF5 (CF_OFF5 + 2 * JT5 * CFP5 * 4)  // 70912
#define C16P5 72
#define PASS5_SMEM (C16_OFF5 + 16 * C16P5 * 2)   // 73216

__global__ __launch_bounds__(256, 3) void pass_route5() {
    extern __shared__ char smb[];
    const uint32_t sb = smem_u32(smb);
    const int jc = blockIdx.x, b = blockIdx.y, tid = threadIdx.x;
    const int lane = tid & 31, w = tid >> 5;
    const int j0 = jc * JT5;

    // stage t16[b]: 16 rows x 1024 halves
    {
        const __half* src = g_t16 + (size_t)b * NCAP * DIN;
        for (int e = tid; e < 2048; e += 256) {
            const int r = e >> 7, c = e & 127;
            cp16(sb + T_OFF5 + r * TPB5 + c * 16, src + (size_t)r * DIN + c * 8);
        }
        cp_commit();
    }
    auto load_panel = [&](int p) {
        const uint32_t base = sb + (uint32_t)(p % NBUF5) * XBUF5;
        const __half* src = g_xh + ((size_t)(b * NIN + j0)) * DIN + p * 64;
        for (int e = tid; e < 512; e += 256) {
            const int j = e >> 3, c = e & 7;
            cp16(base + j * XPB5 + c * 16, src + (size_t)j * DIN + c * 8);
        }
        cp_commit();
    };
    load_panel(0);
    load_panel(1);

    // ---- phase 1: logits(64x16) = X @ t16^T; warp = (m-tile mt, k-half kh) ----
    const int mt = w >> 1, kh = w & 1;
    const uint32_t a_base  = sb + (mt * 16 + (lane & 15)) * XPB5
                             + ((lane >> 4) & 1) * 16 + kh * 64;
    const uint32_t bT_base = sb + T_OFF5 + (lane & 15) * TPB5 + ((lane >> 4) & 1) * 16;

    float la[2][4];
#pragma unroll
    for (int f = 0; f < 2; f++)
#pragma unroll
        for (int q = 0; q < 4; q++) la[f][q] = 0.f;

    for (int p = 0; p < 16; p++) {
        if (p < 14) asm volatile("cp.async.wait_group 1;\n" ::: "memory");
        else        asm volatile("cp.async.wait_group 0;\n" ::: "memory");
        __syncthreads();
        if (p + 2 < 16) load_panel(p + 2);
        const uint32_t xb = (uint32_t)(p % NBUF5) * XBUF5;
#pragma unroll
        for (int s = 0; s < 2; s++) {
            uint32_t af[4], bf[4];
            ldsm_x4(af, a_base + xb + s * 32);
            ldsm_x4(bf, bT_base + p * 128 + kh * 64 + s * 32);
            const uint32_t b0r[2] = {bf[0], bf[2]};
            const uint32_t b1r[2] = {bf[1], bf[3]};
            hmma(la[0], af, b0r);
            hmma(la[1], af, b1r);
        }
    }

    // write k-half logit partials: cf[kh][j][i]
    {
        float* cf = (float*)(smb + CF_OFF5);
        const int jr = mt * 16 + (lane >> 2);
        const int ic = (lane & 3) * 2;
#pragma unroll
        for (int f = 0; f < 2; f++) {
            *(float2*)&cf[(kh * JT5 + jr) * CFP5 + f * 8 + ic] =
                make_float2(la[f][0], la[f][1]);
            *(float2*)&cf[(kh * JT5 + jr + 8) * CFP5 + f * 8 + ic] =
                make_float2(la[f][2], la[f][3]);
        }
    }
    __syncthreads();
    load_panel(0);             // restart x stream for phase 3
    load_panel(1);

    // ---- phase 2: reduce k-halves + softmax over 16 capsules -> c16 [i][j] f16 ----
    {
        const float* cf  = (const float*)(smb + CF_OFF5);
        __half* c16 = (__half*)(smb + C16_OFF5);
#pragma unroll
        for (int r = 0; r < 4; r++) {
            const int j = r * 16 + (tid >> 4), ii = tid & 15;
            const float v = cf[(0 * JT5 + j) * CFP5 + ii] + cf[(1 * JT5 + j) * CFP5 + ii];
            float m = v;
#pragma unroll
            for (int o = 1; o < 16; o <<= 1) m = fmaxf(m, __shfl_xor_sync(0xffffffffu, m, o));
            const float e = expf(v - m);
            float s = e;
#pragma unroll
            for (int o = 1; o < 16; o <<= 1) s += __shfl_xor_sync(0xffffffffu, s, o);
            c16[ii * C16P5 + j] = __float2half_rn(e / s);
        }
    }
    __syncthreads();

    // ---- phase 3: y(16x1024) = c16(16x64) @ X(64x1024); warp = 8-col slab/panel ----
    uint32_t aj[4][4];
    {
        const uint32_t ca = sb + C16_OFF5 + (lane & 15) * (C16P5 * 2) + ((lane >> 4) & 1) * 16;
#pragma unroll
        for (int s = 0; s < 4; s++) ldsm_x4(aj[s], ca + s * 32);
    }

    const uint32_t bx_base = sb + (lane & 15) * XPB5 + w * 16;
    for (int p = 0; p < 16; p++) {
        if (p < 14) asm volatile("cp.async.wait_group 1;\n" ::: "memory");
        else        asm volatile("cp.async.wait_group 0;\n" ::: "memory");
        __syncthreads();
        if (p + 2 < 16) load_panel(p + 2);
        const uint32_t xb = (uint32_t)(p % NBUF5) * XBUF5;
        float ya[4] = {0.f, 0.f, 0.f, 0.f};
#pragma unroll
        for (int s = 0; s < 4; s++) {
            uint32_t bf[2];
            ldsm_x2t(bf, bx_base + xb + s * 16 * XPB5);
            hmma(ya, aj[s], bf);
        }
        const int i0 = lane >> 2;
        const int kc = p * 64 + w * 8 + (lane & 3) * 2;
        *(float2*)&g_ypart[jc][b][i0][kc]     = make_float2(ya[0], ya[1]);
        *(float2*)&g_ypart[jc][b][i0 + 8][kc] = make_float2(ya[2], ya[3]);
    }
}

// ---------------- launch ----------------
extern "C" void kernel_launch(void* const* d_in, const int* in_sizes, int n_in,
                              void* d_out, int out_size) {
    const float* x = (const float*)d_in[0];
    const float* W = (const float*)d_in[1];
    if (in_sizes[0] == DIN * NCAP * DCAP && in_sizes[1] == (int)((size_t)BATCH * NIN * DIN)) {
        const float* t = x; x = W; W = t;
    }
    float* out = (float*)d_out;

    cudaFuncSetAttribute(kA3, cudaFuncAttributeMaxDynamicSharedMemorySize, KA3_SMEM);
    cudaFuncSetAttribute(pass_route5, cudaFuncAttributeMaxDynamicSharedMemorySize, PASS5_SMEM);

    wh16_kernel<<<128, 256>>>(W);
    pass0<<<dim3(8, BATCH), 256>>>(x);
    kA3<<<dim3(NCAP, 8), 512, KA3_SMEM>>>(out, 0);        // iter0: out0, t0
    pass_route5<<<dim3(8, BATCH), 256, PASS5_SMEM>>>();   // iter1: logits/softmax/y1
    kA3<<<dim3(NCAP, 8), 512, KA3_SMEM>>>(out, 1);        // iter1: out1, t1
    pass_route5<<<dim3(8, BATCH), 256, PASS5_SMEM>>>();   // iter2: logits/softmax/y2
    kA3<<<dim3(NCAP, 8), 512, KA3_SMEM>>>(out, 2);        // iter2: final out
}

// round 16
// speedup vs baseline: 1.0630x; 1.0630x over previous
#include <cuda_runtime.h>
#include <cuda_fp16.h>
#include <cstdint>

#define BATCH 64
#define NCAP  16
#define DCAP  64
#define NIN   512
#define DIN   1024

// ---------------- scratch (allocation-free: __device__ globals) ----------------
__device__ __half g_xh[(size_t)BATCH * NIN * DIN];       // 64 MB, x f16 [b][j][k]
__device__ __half g_wh16[(size_t)DIN * NCAP * DCAP];     // 2 MB, W f16 [k][n]
__device__ float  g_xsump[8][BATCH][DIN];                // 2 MB, partial x sums over j
__device__ __half g_t16[(size_t)BATCH * NCAP * DIN];     // 2 MB, t f16 [b][i][k]
__device__ float  g_ypart[8][BATCH][NCAP][DIN];          // 32 MB, y partials

// ---------------- helpers ----------------
__device__ __forceinline__ uint32_t smem_u32(const void* p) {
    uint32_t a;
    asm("{ .reg .u64 t; cvta.to.shared.u64 t, %1; cvt.u32.u64 %0, t; }" : "=r"(a) : "l"(p));
    return a;
}
__device__ __forceinline__ void cp16(uint32_t dst, const void* src) {
    asm volatile("cp.async.cg.shared.global [%0], [%1], 16;\n" :: "r"(dst), "l"(src));
}
__device__ __forceinline__ void cp_commit() { asm volatile("cp.async.commit_group;\n" ::: "memory"); }

__device__ __forceinline__ void hmma(float* d, const uint32_t* a, const uint32_t* b) {
    asm volatile(
        "mma.sync.aligned.m16n8k16.row.col.f32.f16.f16.f32 "
        "{%0,%1,%2,%3}, {%4,%5,%6,%7}, {%8,%9}, {%0,%1,%2,%3};\n"
        : "+f"(d[0]), "+f"(d[1]), "+f"(d[2]), "+f"(d[3])
        : "r"(a[0]), "r"(a[1]), "r"(a[2]), "r"(a[3]), "r"(b[0]), "r"(b[1]));
}
__device__ __forceinline__ void ldsm_x4(uint32_t* r, uint32_t addr) {
    asm volatile("ldmatrix.sync.aligned.m8n8.x4.shared.b16 {%0,%1,%2,%3}, [%4];"
                 : "=r"(r[0]), "=r"(r[1]), "=r"(r[2]), "=r"(r[3]) : "r"(addr));
}
__device__ __forceinline__ void ldsm_x2(uint32_t* r, uint32_t addr) {
    asm volatile("ldmatrix.sync.aligned.m8n8.x2.shared.b16 {%0,%1}, [%2];"
                 : "=r"(r[0]), "=r"(r[1]) : "r"(addr));
}
__device__ __forceinline__ void ldsm_x2t(uint32_t* r, uint32_t addr) {
    asm volatile("ldmatrix.sync.aligned.m8n8.x2.trans.shared.b16 {%0,%1}, [%2];"
                 : "=r"(r[0]), "=r"(r[1]) : "r"(addr));
}

// ---------------- prep: W f32 -> f16 ----------------
__global__ __launch_bounds__(256) void wh16_kernel(const float* __restrict__ W) {
    const size_t n4 = (size_t)DIN * 1024 / 4;
    for (size_t e = (size_t)blockIdx.x * blockDim.x + threadIdx.x; e < n4;
         e += (size_t)gridDim.x * blockDim.x) {
        float4 v = ((const float4*)W)[e];
        __half2* dst = (__half2*)g_wh16 + e * 2;
        dst[0] = __floats2half2_rn(v.x, v.y);
        dst[1] = __floats2half2_rn(v.z, v.w);
    }
}

// ---------------- pass0: xsum partials + x -> f16 ----------------
__global__ __launch_bounds__(256) void pass0(const float* __restrict__ X) {
    const int c = blockIdx.x, b = blockIdx.y, tid = threadIdx.x;
    const size_t rowbase = ((size_t)b * NIN + c * 64) * DIN;
    const float4* xp = (const float4*)(X + rowbase) + tid;
    uint2* xh = (uint2*)(g_xh + rowbase) + tid;
    float4 a = make_float4(0.f, 0.f, 0.f, 0.f);
#pragma unroll 4
    for (int j = 0; j < 64; j++) {
        const float4 v = xp[j * (DIN / 4)];
        a.x += v.x; a.y += v.y; a.z += v.z; a.w += v.w;
        const __half2 h0 = __floats2half2_rn(v.x, v.y);
        const __half2 h1 = __floats2half2_rn(v.z, v.w);
        uint2 u;
        u.x = *(const unsigned*)&h0;
        u.y = *(const unsigned*)&h1;
        xh[j * (DIN / 4)] = u;
    }
    ((float4*)g_xsump[c][b])[tid] = a;
}

// ---------------- kA3: y -> z = y@W_i (mma) -> squash -> t16 = out@W_i^T (mma) ----------------
#define KAB 8
#define WPITB 144
#define YPITH 1032
#define ZPIT  68
#define OPITH 72
#define KY_OFF (DIN * WPITB)               // 147456
#define KZ_OFF (KY_OFF + 16 * YPITH * 2)   // 180480
#define KO_OFF (KZ_OFF + 2 * 8 * ZPIT * 4) // 184832
#define KA3_SMEM (KO_OFF + 16 * OPITH * 2) // 187136

__global__ __launch_bounds__(512) void kA3(float* __restrict__ d_out, int stage) {
    extern __shared__ char smb[];
    const uint32_t sb = smem_u32(smb);
    __half* y16   = (__half*)(smb + KY_OFF);
    float*  zp    = (float*)(smb + KZ_OFF);
    __half* out16 = (__half*)(smb + KO_OFF);

    const int i = blockIdx.x, bg = blockIdx.y, tid = threadIdx.x;
    const int b0 = bg * KAB;
    const int lane = tid & 31, w = tid >> 5;

    {
        const __half* src = g_wh16 + i * 64;
#pragma unroll 4
        for (int e = tid; e < 8192; e += 512) {
            const int k = e >> 3, c = e & 7;
            cp16(sb + k * WPITB + c * 16, src + (size_t)k * 1024 + c * 8);
        }
        cp_commit();
    }

    for (int e = tid; e < 16 * DIN; e += 512) {
        const int r = e >> 10, k = e & 1023;
        float v = 0.f;
        if (r < 8) {
            if (stage == 0) {
#pragma unroll
                for (int p = 0; p < 8; p++) v += g_xsump[p][b0 + r][k];
                v *= (1.f / 16.f);
            } else {
#pragma unroll
                for (int p = 0; p < 8; p++) v += g_ypart[p][b0 + r][i][k];
            }
        }
        y16[r * YPITH + k] = __float2half_rn(v);
    }
    asm volatile("cp.async.wait_group 0;\n" ::: "memory");
    __syncthreads();

    {
        const int kh = w & 1, nt = w >> 1;
        float acc[4] = {0.f, 0.f, 0.f, 0.f};
        const uint32_t a_base = sb + KY_OFF + (uint32_t)(lane & 15) * (YPITH * 2)
                               + ((lane >> 4) & 1) * 16 + kh * 1024;
        const uint32_t b_row0 = (uint32_t)(kh * 512 + (lane & 15));
#pragma unroll
        for (int s = 0; s < 32; s++) {
            uint32_t af[4], bf[2];
            ldsm_x4(af, a_base + s * 32);
            ldsm_x2t(bf, sb + (b_row0 + s * 16) * WPITB + nt * 16);
            hmma(acc, af, bf);
        }
        const int bl = lane >> 2, dc = nt * 8 + (lane & 3) * 2;
        zp[(kh * 8 + bl) * ZPIT + dc]     = acc[0];
        zp[(kh * 8 + bl) * ZPIT + dc + 1] = acc[1];
    }
    __syncthreads();

    if (tid < 256) {
        const int bl = w;
        const float za = zp[(0 * 8 + bl) * ZPIT + 2 * lane]     + zp[(1 * 8 + bl) * ZPIT + 2 * lane];
        const float zb = zp[(0 * 8 + bl) * ZPIT + 2 * lane + 1] + zp[(1 * 8 + bl) * ZPIT + 2 * lane + 1];
        float sq = za * za + zb * zb;
#pragma unroll
        for (int o = 16; o; o >>= 1) sq += __shfl_xor_sync(0xffffffffu, sq, o);
        const float inv = 1.0f / sqrtf(sq + 1e-7f);
        const float ox = za * inv, oy = zb * inv;
        *(half2*)&out16[bl * OPITH + 2 * lane] = __floats2half2_rn(ox, oy);
        if (stage == 2) {
            float2* dp = (float2*)(d_out + ((size_t)(b0 + bl) * NCAP + i) * DCAP);
            dp[lane] = make_float2(ox, oy);
        }
    } else {
        const int idx = tid - 256;
        const int r = 8 + (idx >> 5);
        *(half2*)&out16[r * OPITH + 2 * (idx & 31)] = __floats2half2_rn(0.f, 0.f);
    }
    __syncthreads();
    if (stage == 2) return;

    {
        uint32_t af[4][4];
        const uint32_t oa = sb + KO_OFF + (uint32_t)(lane & 15) * (OPITH * 2)
                           + ((lane >> 4) & 1) * 16;
#pragma unroll
        for (int s = 0; s < 4; s++) ldsm_x4(af[s], oa + s * 32);

        float ta[8][4];
#pragma unroll
        for (int nt = 0; nt < 8; nt++)
#pragma unroll
            for (int q = 0; q < 4; q++) ta[nt][q] = 0.f;

#pragma unroll
        for (int s = 0; s < 4; s++) {
#pragma unroll
            for (int nt = 0; nt < 8; nt++) {
                uint32_t bf[2];
                ldsm_x2(bf, sb + (uint32_t)(w * 64 + nt * 8 + (lane & 7)) * WPITB
                            + ((lane >> 3) & 1) * 16 + s * 32);
                hmma(ta[nt], af[s], bf);
            }
        }

        const int bl = lane >> 2;
#pragma unroll
        for (int nt = 0; nt < 8; nt++) {
            const int k = w * 64 + nt * 8 + (lane & 3) * 2;
            *(half2*)&g_t16[((size_t)(b0 + bl) * NCAP + i) * DIN + k] =
                __floats2half2_rn(ta[nt][0], ta[nt][1]);
        }
    }
}

// ---------------- pass_route6: JT=128, 512 threads (16 warps), 2 CTAs/SM ----------------
#define JT2   128
#define XPB   144
#define XBUF  (JT2 * XPB)                 // 18432
#define NBUF  3
#define T_OFF2 (NBUF * XBUF)              // 55296
#define TPB   2064
#define CF_OFF (T_OFF2 + 16 * TPB)        // 88320
#define CFP   20
#define C16_OFF (CF_OFF + 2 * JT2 * CFP * 4)   // 108800 (k-half partials: 2 x 128 rows)
#define C16P  136
#define PASS6_SMEM (C16_OFF + 16 * C16P * 2)   // 113152

__global__ __launch_bounds__(512, 2) void pass_route6() {
    extern __shared__ char smb[];
    const uint32_t sb = smem_u32(smb);
    const int jc = blockIdx.x, b = blockIdx.y, tid = threadIdx.x;
    const int lane = tid & 31, w = tid >> 5;
    const int j0 = jc * JT2;

    // stage t16[b]: 16 rows x 1024 halves
    {
        const __half* src = g_t16 + (size_t)b * NCAP * DIN;
        for (int e = tid; e < 2048; e += 512) {
            const int r = e >> 7, c = e & 127;
            cp16(sb + T_OFF2 + r * TPB + c * 16, src + (size_t)r * DIN + c * 8);
        }
        cp_commit();
    }
    auto load_panel = [&](int p) {
        const uint32_t base = sb + (uint32_t)(p % NBUF) * XBUF;
        const __half* src = g_xh + ((size_t)(b * NIN + j0)) * DIN + p * 64;
        for (int e = tid; e < 1024; e += 512) {
            const int j = e >> 3, c = e & 7;
            cp16(base + j * XPB + c * 16, src + (size_t)j * DIN + c * 8);
        }
        cp_commit();
    };
    load_panel(0);
    load_panel(1);

    // ---- phase 1: logits(128x16) = X @ t16^T; warp = (m-tile mt 0-7, k-half kh) ----
    const int mt = w >> 1, kh = w & 1;
    const uint32_t a_base  = sb + (mt * 16 + (lane & 15)) * XPB
                             + ((lane >> 4) & 1) * 16 + kh * 64;
    const uint32_t bT_base = sb + T_OFF2 + (lane & 15) * TPB + ((lane >> 4) & 1) * 16;

    float la[2][4];
#pragma unroll
    for (int f = 0; f < 2; f++)
#pragma unroll
        for (int q = 0; q < 4; q++) la[f][q] = 0.f;

    for (int p = 0; p < 16; p++) {
        if (p < 14) asm volatile("cp.async.wait_group 1;\n" ::: "memory");
        else        asm volatile("cp.async.wait_group 0;\n" ::: "memory");
        __syncthreads();
        if (p + 2 < 16) load_panel(p + 2);
        const uint32_t xb = (uint32_t)(p % NBUF) * XBUF;
#pragma unroll
        for (int s = 0; s < 2; s++) {
            uint32_t af[4], bf[4];
            ldsm_x4(af, a_base + xb + s * 32);
            ldsm_x4(bf, bT_base + p * 128 + kh * 64 + s * 32);
            const uint32_t b0r[2] = {bf[0], bf[2]};
            const uint32_t b1r[2] = {bf[1], bf[3]};
            hmma(la[0], af, b0r);
            hmma(la[1], af, b1r);
        }
    }

    // write k-half logit partials cf[kh][j][i]
    {
        float* cf = (float*)(smb + CF_OFF);
        const int jr = mt * 16 + (lane >> 2);
        const int ic = (lane & 3) * 2;
#pragma unroll
        for (int f = 0; f < 2; f++) {
            *(float2*)&cf[(kh * JT2 + jr) * CFP + f * 8 + ic] =
                make_float2(la[f][0], la[f][1]);
            *(float2*)&cf[(kh * JT2 + jr + 8) * CFP + f * 8 + ic] =
                make_float2(la[f][2], la[f][3]);
        }
    }
    __syncthreads();
    load_panel(0);             // restart x stream for phase 3
    load_panel(1);

    // ---- phase 2: reduce k-halves + softmax over 16 capsules -> c16 [i][j] f16 ----
    {
        const float* cf  = (const float*)(smb + CF_OFF);
        __half* c16 = (__half*)(smb + C16_OFF);
#pragma unroll
        for (int r = 0; r < 4; r++) {
            const int j = r * 32 + (tid >> 4), ii = tid & 15;
            const float v = cf[j * CFP + ii] + cf[(JT2 + j) * CFP + ii];
            float m = v;
#pragma unroll
            for (int o = 1; o < 16; o <<= 1) m = fmaxf(m, __shfl_xor_sync(0xffffffffu, m, o));
            const float e = expf(v - m);
            float s = e;
#pragma unroll
            for (int o = 1; o < 16; o <<= 1) s += __shfl_xor_sync(0xffffffffu, s, o);
            c16[ii * C16P + j] = __float2half_rn(e / s);
        }
    }
    __syncthreads();

    // ---- phase 3: y(16x1024) = c16(16x128) @ X(128x1024); warp = (col-slab wc, j-half jh) ----
    const int wc = w >> 1, jh = w & 1;
    uint32_t aj[4][4];
    {
        const uint32_t ca = sb + C16_OFF + (lane & 15) * (C16P * 2) + ((lane >> 4) & 1) * 16;
#pragma unroll
        for (int s = 0; s < 4; s++) ldsm_x4(aj[s], ca + (jh * 4 + s) * 32);
    }

    const uint32_t bx_base = sb + (jh * 64 + (lane & 15)) * XPB + wc * 16;
    for (int p = 0; p < 16; p++) {
        if (p < 14) asm volatile("cp.async.wait_group 1;\n" ::: "memory");
        else        asm volatile("cp.async.wait_group 0;\n" ::: "memory");
        __syncthreads();
        if (p + 2 < 16) load_panel(p + 2);
        const uint32_t xb = (uint32_t)(p % NBUF) * XBUF;
        float ya[4] = {0.f, 0.f, 0.f, 0.f};
#pragma unroll
        for (int s = 0; s < 4; s++) {
            uint32_t bf[2];
            ldsm_x2t(bf, bx_base + xb + s * 16 * XPB);
            hmma(ya, aj[s], bf);
        }
        const int i0 = lane >> 2;
        const int kc = p * 64 + wc * 8 + (lane & 3) * 2;
        *(float2*)&g_ypart[jc * 2 + jh][b][i0][kc]     = make_float2(ya[0], ya[1]);
        *(float2*)&g_ypart[jc * 2 + jh][b][i0 + 8][kc] = make_float2(ya[2], ya[3]);
    }
}

// ---------------- launch ----------------
extern "C" void kernel_launch(void* const* d_in, const int* in_sizes, int n_in,
                              void* d_out, int out_size) {
    const float* x = (const float*)d_in[0];
    const float* W = (const float*)d_in[1];
    if (in_sizes[0] == DIN * NCAP * DCAP && in_sizes[1] == (int)((size_t)BATCH * NIN * DIN)) {
        const float* t = x; x = W; W = t;
    }
    float* out = (float*)d_out;

    cudaFuncSetAttribute(kA3, cudaFuncAttributeMaxDynamicSharedMemorySize, KA3_SMEM);
    cudaFuncSetAttribute(pass_route6, cudaFuncAttributeMaxDynamicSharedMemorySize, PASS6_SMEM);

    wh16_kernel<<<128, 256>>>(W);
    pass0<<<dim3(8, BATCH), 256>>>(x);
    kA3<<<dim3(NCAP, 8), 512, KA3_SMEM>>>(out, 0);        // iter0: out0, t0
    pass_route6<<<dim3(4, BATCH), 512, PASS6_SMEM>>>();   // iter1: logits/softmax/y1
    kA3<<<dim3(NCAP, 8), 512, KA3_SMEM>>>(out, 1);        // iter1: out1, t1
    pass_route6<<<dim3(4, BATCH), 512, PASS6_SMEM>>>();   // iter2: logits/softmax/y2
    kA3<<<dim3(NCAP, 8), 512, KA3_SMEM>>>(out, 2);        // iter2: final out
}